// round 4
// baseline (speedup 1.0000x reference)
#include <cuda_runtime.h>
#include <math.h>

#define DM 256
#define HEADS 8
#define DH 32
#define LEVELS 4
#define POINTS 4
#define DFFN 1024
#define BATCH 8
#define NQ 300
#define NC 16
#define LQ (NQ*NC)          // 4800
#define TOK (BATCH*LQ)      // 38400
#define LEN_IN 5440
#define VROWS (BATCH*LEN_IN) // 43520

// ---------------- scratch (static device memory; no runtime allocation) ----
__device__ float g_t[TOK*DM];        // evolving residual stream
__device__ float g_q[TOK*DM];        // t + query_pos (also reused for sampled CA out)
__device__ float g_x[TOK*DM];        // generic temp
__device__ float g_y[TOK*DM];        // generic temp
__device__ float g_big[TOK*DFFN];    // qkv (768 cols used) / FFN hidden (1024 cols)
__device__ float g_val[VROWS*DM];    // projected value
__device__ float g_attw[TOK*HEADS*LEVELS*POINTS];   // TOK * 128

// ---------------- SGEMM 128x128 tile, 8x8/thread: C = A @ W^T + bias -------
// Requires M%128==0, N%128==0, K%16==0. A:[M,K], W:[N,K], C:[M,ldc].
__global__ __launch_bounds__(256, 2)
void gemm128_kernel(const float* __restrict__ A,
                    const float* __restrict__ W,
                    const float* __restrict__ bias,
                    float* __restrict__ C,
                    int M, int N, int K, int ldc, int relu)
{
    __shared__ float As[2][16][128];
    __shared__ float Bs[2][16][128];

    int tid  = threadIdx.x;
    int bm   = blockIdx.y << 7;
    int bn   = blockIdx.x << 7;
    int warp = tid >> 5, lane = tid & 31;
    int wm = warp & 1, wn = warp >> 1;           // 2x4 warp grid
    int m0 = wm * 64 + (lane >> 2) * 8;          // 8 rows
    int n0 = wn * 32 + (lane & 3) * 8;           // 8 cols

    int lrow = tid & 127;                        // smem row this thread fills
    int lcg  = (tid >> 7) << 3;                  // k-col group: 0 or 8

    const float* Ap = A + (size_t)(bm + lrow) * K + lcg;
    const float* Wp = W + (size_t)(bn + lrow) * K + lcg;

    float acc[8][8];
#pragma unroll
    for (int i = 0; i < 8; i++)
#pragma unroll
        for (int j = 0; j < 8; j++) acc[i][j] = 0.f;

    const int NIT = K >> 4;
    float4 pa0, pa1, pb0, pb1;

    // first tile
    pa0 = *(const float4*)(Ap);     pa1 = *(const float4*)(Ap + 4);
    pb0 = *(const float4*)(Wp);     pb1 = *(const float4*)(Wp + 4);
    {
        float ta[8] = {pa0.x,pa0.y,pa0.z,pa0.w,pa1.x,pa1.y,pa1.z,pa1.w};
        float tb[8] = {pb0.x,pb0.y,pb0.z,pb0.w,pb1.x,pb1.y,pb1.z,pb1.w};
#pragma unroll
        for (int j = 0; j < 8; j++) { As[0][lcg+j][lrow] = ta[j]; Bs[0][lcg+j][lrow] = tb[j]; }
    }
    __syncthreads();

    int buf = 0;
    for (int it = 1; it < NIT; ++it) {
        const float* Ait = Ap + (it << 4);
        const float* Wit = Wp + (it << 4);
        pa0 = *(const float4*)(Ait);     pa1 = *(const float4*)(Ait + 4);
        pb0 = *(const float4*)(Wit);     pb1 = *(const float4*)(Wit + 4);

#pragma unroll
        for (int k = 0; k < 16; k++) {
            float4 av0 = *(const float4*)&As[buf][k][m0];
            float4 av1 = *(const float4*)&As[buf][k][m0 + 4];
            float4 bv0 = *(const float4*)&Bs[buf][k][n0];
            float4 bv1 = *(const float4*)&Bs[buf][k][n0 + 4];
            float a[8] = {av0.x,av0.y,av0.z,av0.w,av1.x,av1.y,av1.z,av1.w};
            float b[8] = {bv0.x,bv0.y,bv0.z,bv0.w,bv1.x,bv1.y,bv1.z,bv1.w};
#pragma unroll
            for (int i = 0; i < 8; i++)
#pragma unroll
                for (int j = 0; j < 8; j++) acc[i][j] += a[i] * b[j];
        }

        int nb = buf ^ 1;
        {
            float ta[8] = {pa0.x,pa0.y,pa0.z,pa0.w,pa1.x,pa1.y,pa1.z,pa1.w};
            float tb[8] = {pb0.x,pb0.y,pb0.z,pb0.w,pb1.x,pb1.y,pb1.z,pb1.w};
#pragma unroll
            for (int j = 0; j < 8; j++) { As[nb][lcg+j][lrow] = ta[j]; Bs[nb][lcg+j][lrow] = tb[j]; }
        }
        __syncthreads();
        buf = nb;
    }

    // last tile compute
#pragma unroll
    for (int k = 0; k < 16; k++) {
        float4 av0 = *(const float4*)&As[buf][k][m0];
        float4 av1 = *(const float4*)&As[buf][k][m0 + 4];
        float4 bv0 = *(const float4*)&Bs[buf][k][n0];
        float4 bv1 = *(const float4*)&Bs[buf][k][n0 + 4];
        float a[8] = {av0.x,av0.y,av0.z,av0.w,av1.x,av1.y,av1.z,av1.w};
        float b[8] = {bv0.x,bv0.y,bv0.z,bv0.w,bv1.x,bv1.y,bv1.z,bv1.w};
#pragma unroll
        for (int i = 0; i < 8; i++)
#pragma unroll
            for (int j = 0; j < 8; j++) acc[i][j] += a[i] * b[j];
    }

    // epilogue: bias (+relu), vectorized stores
    float4 bi0 = *(const float4*)(bias + bn + n0);
    float4 bi1 = *(const float4*)(bias + bn + n0 + 4);
    float bb[8] = {bi0.x,bi0.y,bi0.z,bi0.w,bi1.x,bi1.y,bi1.z,bi1.w};
    float lo = relu ? 0.f : -__int_as_float(0x7f800000);  // -inf when no relu
#pragma unroll
    for (int i = 0; i < 8; i++) {
        size_t row = (size_t)(bm + m0 + i);
        float4 o0, o1;
        float v[8];
#pragma unroll
        for (int j = 0; j < 8; j++) {
            v[j] = fmaxf(acc[i][j] + bb[j], lo);
        }
        o0.x=v[0]; o0.y=v[1]; o0.z=v[2]; o0.w=v[3];
        o1.x=v[4]; o1.y=v[5]; o1.z=v[6]; o1.w=v[7];
        *(float4*)&C[row * ldc + bn + n0]     = o0;
        *(float4*)&C[row * ldc + bn + n0 + 4] = o1;
    }
}

// ---------------- elementwise: q = a + b, optionally t = a ------------------
__global__ void add_copy_kernel(const float* __restrict__ a,
                                const float* __restrict__ b,
                                float* __restrict__ q,
                                float* __restrict__ t, int n)
{
    int i = blockIdx.x * blockDim.x + threadIdx.x;
    if (i < n) {
        float av = a[i];
        q[i] = av + b[i];
        if (t) t[i] = av;
    }
}

// ---------------- zero masked value rows -----------------------------------
__global__ void mask_kernel(float* __restrict__ val,
                            const unsigned char* __restrict__ mask, long n)
{
    long i = (long)blockIdx.x * blockDim.x + threadIdx.x;
    if (i < n) {
        if (mask[i >> 8]) val[i] = 0.f;
    }
}

// ---------------- self-attention over 16-token sequences --------------------
__global__ void self_attn_kernel(const float* __restrict__ qkv,
                                 float* __restrict__ out)
{
    __shared__ float sQ[NC][DM];
    __shared__ float sK[NC][DM];
    __shared__ float sV[NC][DM];
    int s = blockIdx.x;
    int tid = threadIdx.x;
    const float* base = qkv + (size_t)s * NC * 768;
    for (int idx = tid; idx < NC * DM; idx += 128) {
        int i = idx >> 8, c = idx & 255;
        sQ[i][c] = base[i * 768 + c];
        sK[i][c] = base[i * 768 + 256 + c];
        sV[i][c] = base[i * 768 + 512 + c];
    }
    __syncthreads();

    int h = tid >> 4, i = tid & 15;
    const float scale = 0.1767766952966369f;  // 1/sqrt(32)
    float sc[NC];
    float mx = -1e30f;
#pragma unroll
    for (int j = 0; j < NC; j++) {
        float acc = 0.f;
#pragma unroll
        for (int d = 0; d < DH; d++) acc += sQ[i][h*DH + d] * sK[j][h*DH + d];
        acc *= scale;
        sc[j] = acc;
        mx = fmaxf(mx, acc);
    }
    float sum = 0.f;
#pragma unroll
    for (int j = 0; j < NC; j++) { sc[j] = expf(sc[j] - mx); sum += sc[j]; }
    float inv = 1.f / sum;
#pragma unroll
    for (int d = 0; d < DH; d++) {
        float acc = 0.f;
#pragma unroll
        for (int j = 0; j < NC; j++) acc += sc[j] * sV[j][h*DH + d];
        out[((size_t)s * NC + i) * DM + h*DH + d] = acc * inv;
    }
}

// ---------------- add + layernorm ------------------------------------------
__global__ void add_ln_kernel(const float* __restrict__ a,
                              const float* __restrict__ b,
                              const float* __restrict__ w,
                              const float* __restrict__ bb,
                              float* __restrict__ out)
{
    __shared__ float sred[8];
    __shared__ float smean, svar;
    int row = blockIdx.x, tid = threadIdx.x;    // 256 threads
    size_t idx = (size_t)row * DM + tid;
    float x = a[idx] + b[idx];
    float v = x;
#pragma unroll
    for (int o = 16; o; o >>= 1) v += __shfl_xor_sync(0xffffffffu, v, o);
    if ((tid & 31) == 0) sred[tid >> 5] = v;
    __syncthreads();
    if (tid == 0) {
        float s = 0.f;
#pragma unroll
        for (int k = 0; k < 8; k++) s += sred[k];
        smean = s * (1.f / DM);
    }
    __syncthreads();
    float d = x - smean;
    v = d * d;
#pragma unroll
    for (int o = 16; o; o >>= 1) v += __shfl_xor_sync(0xffffffffu, v, o);
    if ((tid & 31) == 0) sred[tid >> 5] = v;
    __syncthreads();
    if (tid == 0) {
        float s = 0.f;
#pragma unroll
        for (int k = 0; k < 8; k++) s += sred[k];
        svar = s * (1.f / DM);
    }
    __syncthreads();
    out[idx] = d * rsqrtf(svar + 1e-5f) * w[tid] + bb[tid];
}

// ---------------- deformable sampling ---------------------------------------
__global__ void deform_kernel(const float* __restrict__ off,
                              const float* __restrict__ attw,
                              const float* __restrict__ refp,
                              const float* __restrict__ val,
                              float* __restrict__ out)
{
    __shared__ float saw[HEADS][16];
    int token = blockIdx.x;
    int bidx  = token / LQ;
    int tid = threadIdx.x;
    int h = tid >> 5, lane = tid & 31;
    int j = lane & 15;

    float w = attw[(size_t)token * (HEADS*16) + h*16 + j];
    float mx = w;
#pragma unroll
    for (int o = 8; o; o >>= 1) mx = fmaxf(mx, __shfl_xor_sync(0xffffffffu, mx, o));
    float e = expf(w - mx);
    float s = e;
#pragma unroll
    for (int o = 8; o; o >>= 1) s += __shfl_xor_sync(0xffffffffu, s, o);
    if (lane < 16) saw[h][lane] = e / s;
    __syncwarp();

    const int Hs[4]     = {64, 32, 16, 8};
    const int Ws[4]     = {64, 32, 16, 8};
    const int starts[4] = {0, 4096, 5120, 5376};

    const float* offp = off + (size_t)token * DM + h * 32;
    const float* refb = refp + (size_t)token * (LEVELS*2);
    const float* vb = val + ((size_t)bidx * LEN_IN) * DM + h * DH + lane;

    float acc = 0.f;
#pragma unroll
    for (int l = 0; l < LEVELS; l++) {
        int H_ = Hs[l], W_ = Ws[l];
        float rx = refb[l*2 + 0], ry = refb[l*2 + 1];
        const float* vlev = vb + (size_t)starts[l] * DM;
#pragma unroll
        for (int p = 0; p < POINTS; p++) {
            float ox = offp[(l*4 + p)*2 + 0];
            float oy = offp[(l*4 + p)*2 + 1];
            float gx = (rx + ox / W_) * W_ - 0.5f;
            float gy = (ry + oy / H_) * H_ - 0.5f;
            float fx = floorf(gx), fy = floorf(gy);
            int x0 = (int)fx, y0 = (int)fy;
            float ax = gx - fx, ay = gy - fy;
            float aw = saw[h][l*4 + p];
            bool xin0 = (x0 >= 0) && (x0 < W_);
            bool xin1 = (x0 + 1 >= 0) && (x0 + 1 < W_);
            bool yin0 = (y0 >= 0) && (y0 < H_);
            bool yin1 = (y0 + 1 >= 0) && (y0 + 1 < H_);
            float v00 = (xin0 && yin0) ? vlev[(size_t)(y0*W_ + x0) * DM] : 0.f;
            float v01 = (xin1 && yin0) ? vlev[(size_t)(y0*W_ + x0 + 1) * DM] : 0.f;
            float v10 = (xin0 && yin1) ? vlev[(size_t)((y0+1)*W_ + x0) * DM] : 0.f;
            float v11 = (xin1 && yin1) ? vlev[(size_t)((y0+1)*W_ + x0 + 1) * DM] : 0.f;
            float sample = v00*(1.f-ax)*(1.f-ay) + v01*ax*(1.f-ay)
                         + v10*(1.f-ax)*ay       + v11*ax*ay;
            acc += aw * sample;
        }
    }
    out[(size_t)token * DM + h * DH + lane] = acc;
}

// ---------------------------------------------------------------------------
extern "C" void kernel_launch(void* const* d_in, const int* in_sizes, int n_in,
                              void* d_out, int out_size)
{
    const float* tgt   = (const float*)d_in[0];
    const float* qpos  = (const float*)d_in[1];
    const float* refp  = (const float*)d_in[2];
    const float* src   = (const float*)d_in[3];
    const unsigned char* mask = (const unsigned char*)d_in[6];
    const float* sa_in_w  = (const float*)d_in[7];
    const float* sa_in_b  = (const float*)d_in[8];
    const float* sa_out_w = (const float*)d_in[9];
    const float* sa_out_b = (const float*)d_in[10];
    const float* norm2_w  = (const float*)d_in[11];
    const float* norm2_b  = (const float*)d_in[12];
    const float* ca_value_w = (const float*)d_in[13];
    const float* ca_value_b = (const float*)d_in[14];
    const float* ca_off_w   = (const float*)d_in[15];
    const float* ca_off_b   = (const float*)d_in[16];
    const float* ca_attw_w  = (const float*)d_in[17];
    const float* ca_attw_b  = (const float*)d_in[18];
    const float* ca_out_w   = (const float*)d_in[19];
    const float* ca_out_b   = (const float*)d_in[20];
    const float* norm1_w    = (const float*)d_in[21];
    const float* norm1_b    = (const float*)d_in[22];
    const float* lin1_w     = (const float*)d_in[23];
    const float* lin1_b     = (const float*)d_in[24];
    const float* lin2_w     = (const float*)d_in[25];
    const float* lin2_b     = (const float*)d_in[26];
    const float* norm3_w    = (const float*)d_in[27];
    const float* norm3_b    = (const float*)d_in[28];
    float* out = (float*)d_out;

    float *gt, *gq, *gx, *gy, *gbig, *gval, *gattw;
    cudaGetSymbolAddress((void**)&gt,   g_t);
    cudaGetSymbolAddress((void**)&gq,   g_q);
    cudaGetSymbolAddress((void**)&gx,   g_x);
    cudaGetSymbolAddress((void**)&gy,   g_y);
    cudaGetSymbolAddress((void**)&gbig, g_big);
    cudaGetSymbolAddress((void**)&gval, g_val);
    cudaGetSymbolAddress((void**)&gattw, g_attw);

    const int nTD = TOK * DM;   // 9,830,400

    // ---- stage 1: self-attention -------------------------------------------
    add_copy_kernel<<<(nTD + 255) / 256, 256>>>(tgt, qpos, gq, gt, nTD);
    // QK projection (rows 0..511 of sa_in_w), from q
    {
        dim3 grid(512 / 128, TOK / 128);
        gemm128_kernel<<<grid, 256>>>(gq, sa_in_w, sa_in_b, gbig, TOK, 512, DM, 768, 0);
    }
    // V projection (rows 512..767), from t
    {
        dim3 grid(256 / 128, TOK / 128);
        gemm128_kernel<<<grid, 256>>>(gt, sa_in_w + (size_t)512 * DM, sa_in_b + 512,
                                      gbig + 512, TOK, 256, DM, 768, 0);
    }
    self_attn_kernel<<<BATCH * NQ, 128>>>(gbig, gx);
    {
        dim3 grid(256 / 128, TOK / 128);
        gemm128_kernel<<<grid, 256>>>(gx, sa_out_w, sa_out_b, gy, TOK, 256, DM, 256, 0);
    }
    add_ln_kernel<<<TOK, 256>>>(gt, gy, norm2_w, norm2_b, gt);

    // ---- stage 2: deformable cross-attention -------------------------------
    add_copy_kernel<<<(nTD + 255) / 256, 256>>>(gt, qpos, gq, (float*)0, nTD);
    {
        dim3 grid(256 / 128, VROWS / 128);
        gemm128_kernel<<<grid, 256>>>(src, ca_value_w, ca_value_b, gval, VROWS, 256, DM, 256, 0);
    }
    {
        long n = (long)VROWS * DM;
        mask_kernel<<<(unsigned)((n + 255) / 256), 256>>>(gval, mask, n);
    }
    {
        dim3 grid(256 / 128, TOK / 128);
        gemm128_kernel<<<grid, 256>>>(gq, ca_off_w, ca_off_b, gx, TOK, 256, DM, 256, 0);
    }
    {
        dim3 grid(128 / 128, TOK / 128);
        gemm128_kernel<<<grid, 256>>>(gq, ca_attw_w, ca_attw_b, gattw, TOK, 128, DM, 128, 0);
    }
    deform_kernel<<<TOK, 256>>>(gx, gattw, refp, gval, gq);
    {
        dim3 grid(256 / 128, TOK / 128);
        gemm128_kernel<<<grid, 256>>>(gq, ca_out_w, ca_out_b, gx, TOK, 256, DM, 256, 0);
    }
    add_ln_kernel<<<TOK, 256>>>(gt, gx, norm1_w, norm1_b, gt);

    // ---- stage 3: FFN ------------------------------------------------------
    {
        dim3 grid(DFFN / 128, TOK / 128);
        gemm128_kernel<<<grid, 256>>>(gt, lin1_w, lin1_b, gbig, TOK, DFFN, DM, DFFN, 1);
    }
    {
        dim3 grid(256 / 128, TOK / 128);
        gemm128_kernel<<<grid, 256>>>(gbig, lin2_w, lin2_b, gx, TOK, 256, DFFN, 256, 0);
    }
    add_ln_kernel<<<TOK, 256>>>(gt, gx, norm3_w, norm3_b, out);
}

// round 5
// speedup vs baseline: 1.9232x; 1.9232x over previous
#include <cuda_runtime.h>
#include <math.h>

#define DM 256
#define HEADS 8
#define DH 32
#define LEVELS 4
#define POINTS 4
#define DFFN 1024
#define BATCH 8
#define NQ 300
#define NC 16
#define LQ (NQ*NC)          // 4800
#define TOK (BATCH*LQ)      // 38400
#define LEN_IN 5440
#define VROWS (BATCH*LEN_IN) // 43520

// ---------------- scratch (static device memory; no runtime allocation) ----
__device__ float g_t[TOK*DM];
__device__ float g_q[TOK*DM];
__device__ float g_x[TOK*DM];
__device__ float g_y[TOK*DM];
__device__ float g_big[TOK*DFFN];
__device__ float g_val[VROWS*DM];
__device__ float g_attw[TOK*HEADS*LEVELS*POINTS];

// ---------------- tf32 helpers ---------------------------------------------
__device__ __forceinline__ unsigned tf32_rna(float x) {
    unsigned r;
    asm("cvt.rna.tf32.f32 %0, %1;" : "=r"(r) : "f"(x));
    return r;
}

__device__ __forceinline__ void mma8(float* c, const unsigned* a, const unsigned* b) {
    asm volatile(
        "mma.sync.aligned.m16n8k8.row.col.f32.tf32.tf32.f32 "
        "{%0,%1,%2,%3}, {%4,%5,%6,%7}, {%8,%9}, {%0,%1,%2,%3};\n"
        : "+f"(c[0]), "+f"(c[1]), "+f"(c[2]), "+f"(c[3])
        : "r"(a[0]), "r"(a[1]), "r"(a[2]), "r"(a[3]), "r"(b[0]), "r"(b[1]));
}

// ---------------- 3xTF32 GEMM, 128x128 tile: C = A @ W^T + bias ------------
// Requires M%128==0, N%128==0, K%16==0. A:[M,K], W:[N,K], C:[M,ldc].
// fp32 emulated via hi/lo tf32 split: ab = ah*bh + ah*bl + al*bh (+O(2^-22)).
#define SPAD 136
__global__ __launch_bounds__(256)
void gemm_tc_kernel(const float* __restrict__ A,
                    const float* __restrict__ W,
                    const float* __restrict__ bias,
                    float* __restrict__ C,
                    int M, int N, int K, int ldc, int relu)
{
    __shared__ unsigned Ah[16][SPAD], Al[16][SPAD];
    __shared__ unsigned Bh[16][SPAD], Bl[16][SPAD];

    int tid  = threadIdx.x;                     // 256 threads = 8 warps
    int bm   = blockIdx.y << 7;
    int bn   = blockIdx.x << 7;
    int warp = tid >> 5, lane = tid & 31;
    int wm = warp & 1, wn = warp >> 1;          // 2 (M) x 4 (N) warps
    int g = lane >> 2, t = lane & 3;            // mma thread coords

    int lrow = tid >> 2;                        // 0..63
    int kc   = (tid & 3) << 2;                  // 0,4,8,12

    const float* Ap0 = A + (size_t)(bm + lrow) * K + kc;
    const float* Ap1 = A + (size_t)(bm + lrow + 64) * K + kc;
    const float* Wp0 = W + (size_t)(bn + lrow) * K + kc;
    const float* Wp1 = W + (size_t)(bn + lrow + 64) * K + kc;

    float c[4][4][4];
#pragma unroll
    for (int mt = 0; mt < 4; mt++)
#pragma unroll
        for (int nt = 0; nt < 4; nt++)
#pragma unroll
            for (int r = 0; r < 4; r++) c[mt][nt][r] = 0.f;

    const int NIT = K >> 4;

    float4 pa0 = *(const float4*)(Ap0);
    float4 pa1 = *(const float4*)(Ap1);
    float4 pb0 = *(const float4*)(Wp0);
    float4 pb1 = *(const float4*)(Wp1);

    for (int it = 0; it < NIT; ++it) {
        // store current tile (hi/lo split)
        {
            float xa0[4] = {pa0.x,pa0.y,pa0.z,pa0.w};
            float xa1[4] = {pa1.x,pa1.y,pa1.z,pa1.w};
            float xb0[4] = {pb0.x,pb0.y,pb0.z,pb0.w};
            float xb1[4] = {pb1.x,pb1.y,pb1.z,pb1.w};
#pragma unroll
            for (int j = 0; j < 4; j++) {
                unsigned h;
                h = tf32_rna(xa0[j]);
                Ah[kc+j][lrow]      = h;
                Al[kc+j][lrow]      = __float_as_uint(xa0[j] - __uint_as_float(h));
                h = tf32_rna(xa1[j]);
                Ah[kc+j][lrow+64]   = h;
                Al[kc+j][lrow+64]   = __float_as_uint(xa1[j] - __uint_as_float(h));
                h = tf32_rna(xb0[j]);
                Bh[kc+j][lrow]      = h;
                Bl[kc+j][lrow]      = __float_as_uint(xb0[j] - __uint_as_float(h));
                h = tf32_rna(xb1[j]);
                Bh[kc+j][lrow+64]   = h;
                Bl[kc+j][lrow+64]   = __float_as_uint(xb1[j] - __uint_as_float(h));
            }
        }
        __syncthreads();

        // prefetch next tile while computing
        if (it + 1 < NIT) {
            int off = (it + 1) << 4;
            pa0 = *(const float4*)(Ap0 + off);
            pa1 = *(const float4*)(Ap1 + off);
            pb0 = *(const float4*)(Wp0 + off);
            pb1 = *(const float4*)(Wp1 + off);
        }

#pragma unroll
        for (int ks = 0; ks < 16; ks += 8) {
            unsigned ah[4][4], al[4][4], bh[4][2], bl[4][2];
#pragma unroll
            for (int mt = 0; mt < 4; mt++) {
                int m = wm*64 + mt*16 + g;
                ah[mt][0] = Ah[ks+t][m];   ah[mt][1] = Ah[ks+t][m+8];
                ah[mt][2] = Ah[ks+t+4][m]; ah[mt][3] = Ah[ks+t+4][m+8];
                al[mt][0] = Al[ks+t][m];   al[mt][1] = Al[ks+t][m+8];
                al[mt][2] = Al[ks+t+4][m]; al[mt][3] = Al[ks+t+4][m+8];
            }
#pragma unroll
            for (int nt = 0; nt < 4; nt++) {
                int n = wn*32 + nt*8 + g;
                bh[nt][0] = Bh[ks+t][n];   bh[nt][1] = Bh[ks+t+4][n];
                bl[nt][0] = Bl[ks+t][n];   bl[nt][1] = Bl[ks+t+4][n];
            }
#pragma unroll
            for (int mt = 0; mt < 4; mt++)
#pragma unroll
                for (int nt = 0; nt < 4; nt++) {
                    mma8(c[mt][nt], ah[mt], bh[nt]);
                    mma8(c[mt][nt], ah[mt], bl[nt]);
                    mma8(c[mt][nt], al[mt], bh[nt]);
                }
        }
        __syncthreads();
    }

    // epilogue: bias (+relu)
    float lob = relu ? 0.f : __int_as_float(0xff800000);  // -inf if no relu
#pragma unroll
    for (int mt = 0; mt < 4; mt++) {
        int row0 = bm + wm*64 + mt*16 + g;
#pragma unroll
        for (int nt = 0; nt < 4; nt++) {
            int col = bn + wn*32 + nt*8 + 2*t;
            float2 bi = *(const float2*)(bias + col);
            float2 o0, o1;
            o0.x = fmaxf(c[mt][nt][0] + bi.x, lob);
            o0.y = fmaxf(c[mt][nt][1] + bi.y, lob);
            o1.x = fmaxf(c[mt][nt][2] + bi.x, lob);
            o1.y = fmaxf(c[mt][nt][3] + bi.y, lob);
            *(float2*)&C[(size_t)row0 * ldc + col]       = o0;
            *(float2*)&C[(size_t)(row0+8) * ldc + col]   = o1;
        }
    }
}

// ---------------- elementwise: q = a + b, optionally t = a ------------------
__global__ void add_copy_kernel(const float* __restrict__ a,
                                const float* __restrict__ b,
                                float* __restrict__ q,
                                float* __restrict__ t, int n)
{
    int i = blockIdx.x * blockDim.x + threadIdx.x;
    if (i < n) {
        float av = a[i];
        q[i] = av + b[i];
        if (t) t[i] = av;
    }
}

// ---------------- zero masked value rows -----------------------------------
__global__ void mask_kernel(float* __restrict__ val,
                            const unsigned char* __restrict__ mask, long n)
{
    long i = (long)blockIdx.x * blockDim.x + threadIdx.x;
    if (i < n) {
        if (mask[i >> 8]) val[i] = 0.f;
    }
}

// ---------------- self-attention over 16-token sequences --------------------
__global__ void self_attn_kernel(const float* __restrict__ qkv,
                                 float* __restrict__ out)
{
    __shared__ float sQ[NC][DM];
    __shared__ float sK[NC][DM];
    __shared__ float sV[NC][DM];
    int s = blockIdx.x;
    int tid = threadIdx.x;
    const float* base = qkv + (size_t)s * NC * 768;
    for (int idx = tid; idx < NC * DM; idx += 128) {
        int i = idx >> 8, cc = idx & 255;
        sQ[i][cc] = base[i * 768 + cc];
        sK[i][cc] = base[i * 768 + 256 + cc];
        sV[i][cc] = base[i * 768 + 512 + cc];
    }
    __syncthreads();

    int h = tid >> 4, i = tid & 15;
    const float scale = 0.1767766952966369f;  // 1/sqrt(32)
    float sc[NC];
    float mx = -1e30f;
#pragma unroll
    for (int j = 0; j < NC; j++) {
        float acc = 0.f;
#pragma unroll
        for (int d = 0; d < DH; d++) acc += sQ[i][h*DH + d] * sK[j][h*DH + d];
        acc *= scale;
        sc[j] = acc;
        mx = fmaxf(mx, acc);
    }
    float sum = 0.f;
#pragma unroll
    for (int j = 0; j < NC; j++) { sc[j] = expf(sc[j] - mx); sum += sc[j]; }
    float inv = 1.f / sum;
#pragma unroll
    for (int d = 0; d < DH; d++) {
        float acc = 0.f;
#pragma unroll
        for (int j = 0; j < NC; j++) acc += sc[j] * sV[j][h*DH + d];
        out[((size_t)s * NC + i) * DM + h*DH + d] = acc * inv;
    }
}

// ---------------- add + layernorm ------------------------------------------
__global__ void add_ln_kernel(const float* __restrict__ a,
                              const float* __restrict__ b,
                              const float* __restrict__ w,
                              const float* __restrict__ bb,
                              float* __restrict__ out)
{
    __shared__ float sred[8];
    __shared__ float smean, svar;
    int row = blockIdx.x, tid = threadIdx.x;    // 256 threads
    size_t idx = (size_t)row * DM + tid;
    float x = a[idx] + b[idx];
    float v = x;
#pragma unroll
    for (int o = 16; o; o >>= 1) v += __shfl_xor_sync(0xffffffffu, v, o);
    if ((tid & 31) == 0) sred[tid >> 5] = v;
    __syncthreads();
    if (tid == 0) {
        float s = 0.f;
#pragma unroll
        for (int k = 0; k < 8; k++) s += sred[k];
        smean = s * (1.f / DM);
    }
    __syncthreads();
    float d = x - smean;
    v = d * d;
#pragma unroll
    for (int o = 16; o; o >>= 1) v += __shfl_xor_sync(0xffffffffu, v, o);
    if ((tid & 31) == 0) sred[tid >> 5] = v;
    __syncthreads();
    if (tid == 0) {
        float s = 0.f;
#pragma unroll
        for (int k = 0; k < 8; k++) s += sred[k];
        svar = s * (1.f / DM);
    }
    __syncthreads();
    out[idx] = d * rsqrtf(svar + 1e-5f) * w[tid] + bb[tid];
}

// ---------------- deformable sampling ---------------------------------------
__global__ void deform_kernel(const float* __restrict__ off,
                              const float* __restrict__ attw,
                              const float* __restrict__ refp,
                              const float* __restrict__ val,
                              float* __restrict__ out)
{
    __shared__ float saw[HEADS][16];
    int token = blockIdx.x;
    int bidx  = token / LQ;
    int tid = threadIdx.x;
    int h = tid >> 5, lane = tid & 31;
    int j = lane & 15;

    float w = attw[(size_t)token * (HEADS*16) + h*16 + j];
    float mx = w;
#pragma unroll
    for (int o = 8; o; o >>= 1) mx = fmaxf(mx, __shfl_xor_sync(0xffffffffu, mx, o));
    float e = expf(w - mx);
    float s = e;
#pragma unroll
    for (int o = 8; o; o >>= 1) s += __shfl_xor_sync(0xffffffffu, s, o);
    if (lane < 16) saw[h][lane] = e / s;
    __syncwarp();

    const int Hs[4]     = {64, 32, 16, 8};
    const int Ws[4]     = {64, 32, 16, 8};
    const int starts[4] = {0, 4096, 5120, 5376};

    const float* offp = off + (size_t)token * DM + h * 32;
    const float* refb = refp + (size_t)token * (LEVELS*2);
    const float* vb = val + ((size_t)bidx * LEN_IN) * DM + h * DH + lane;

    float acc = 0.f;
#pragma unroll
    for (int l = 0; l < LEVELS; l++) {
        int H_ = Hs[l], W_ = Ws[l];
        float rx = refb[l*2 + 0], ry = refb[l*2 + 1];
        const float* vlev = vb + (size_t)starts[l] * DM;
#pragma unroll
        for (int p = 0; p < POINTS; p++) {
            float ox = offp[(l*4 + p)*2 + 0];
            float oy = offp[(l*4 + p)*2 + 1];
            float gx = (rx + ox / W_) * W_ - 0.5f;
            float gy = (ry + oy / H_) * H_ - 0.5f;
            float fx = floorf(gx), fy = floorf(gy);
            int x0 = (int)fx, y0 = (int)fy;
            float ax = gx - fx, ay = gy - fy;
            float aw = saw[h][l*4 + p];
            bool xin0 = (x0 >= 0) && (x0 < W_);
            bool xin1 = (x0 + 1 >= 0) && (x0 + 1 < W_);
            bool yin0 = (y0 >= 0) && (y0 < H_);
            bool yin1 = (y0 + 1 >= 0) && (y0 + 1 < H_);
            float v00 = (xin0 && yin0) ? vlev[(size_t)(y0*W_ + x0) * DM] : 0.f;
            float v01 = (xin1 && yin0) ? vlev[(size_t)(y0*W_ + x0 + 1) * DM] : 0.f;
            float v10 = (xin0 && yin1) ? vlev[(size_t)((y0+1)*W_ + x0) * DM] : 0.f;
            float v11 = (xin1 && yin1) ? vlev[(size_t)((y0+1)*W_ + x0 + 1) * DM] : 0.f;
            float sample = v00*(1.f-ax)*(1.f-ay) + v01*ax*(1.f-ay)
                         + v10*(1.f-ax)*ay       + v11*ax*ay;
            acc += aw * sample;
        }
    }
    out[(size_t)token * DM + h * DH + lane] = acc;
}

// ---------------------------------------------------------------------------
extern "C" void kernel_launch(void* const* d_in, const int* in_sizes, int n_in,
                              void* d_out, int out_size)
{
    const float* tgt   = (const float*)d_in[0];
    const float* qpos  = (const float*)d_in[1];
    const float* refp  = (const float*)d_in[2];
    const float* src   = (const float*)d_in[3];
    const unsigned char* mask = (const unsigned char*)d_in[6];
    const float* sa_in_w  = (const float*)d_in[7];
    const float* sa_in_b  = (const float*)d_in[8];
    const float* sa_out_w = (const float*)d_in[9];
    const float* sa_out_b = (const float*)d_in[10];
    const float* norm2_w  = (const float*)d_in[11];
    const float* norm2_b  = (const float*)d_in[12];
    const float* ca_value_w = (const float*)d_in[13];
    const float* ca_value_b = (const float*)d_in[14];
    const float* ca_off_w   = (const float*)d_in[15];
    const float* ca_off_b   = (const float*)d_in[16];
    const float* ca_attw_w  = (const float*)d_in[17];
    const float* ca_attw_b  = (const float*)d_in[18];
    const float* ca_out_w   = (const float*)d_in[19];
    const float* ca_out_b   = (const float*)d_in[20];
    const float* norm1_w    = (const float*)d_in[21];
    const float* norm1_b    = (const float*)d_in[22];
    const float* lin1_w     = (const float*)d_in[23];
    const float* lin1_b     = (const float*)d_in[24];
    const float* lin2_w     = (const float*)d_in[25];
    const float* lin2_b     = (const float*)d_in[26];
    const float* norm3_w    = (const float*)d_in[27];
    const float* norm3_b    = (const float*)d_in[28];
    float* out = (float*)d_out;

    float *gt, *gq, *gx, *gy, *gbig, *gval, *gattw;
    cudaGetSymbolAddress((void**)&gt,   g_t);
    cudaGetSymbolAddress((void**)&gq,   g_q);
    cudaGetSymbolAddress((void**)&gx,   g_x);
    cudaGetSymbolAddress((void**)&gy,   g_y);
    cudaGetSymbolAddress((void**)&gbig, g_big);
    cudaGetSymbolAddress((void**)&gval, g_val);
    cudaGetSymbolAddress((void**)&gattw, g_attw);

    const int nTD = TOK * DM;   // 9,830,400

    // ---- stage 1: self-attention -------------------------------------------
    add_copy_kernel<<<(nTD + 255) / 256, 256>>>(tgt, qpos, gq, gt, nTD);
    {
        dim3 grid(512 / 128, TOK / 128);
        gemm_tc_kernel<<<grid, 256>>>(gq, sa_in_w, sa_in_b, gbig, TOK, 512, DM, 768, 0);
    }
    {
        dim3 grid(256 / 128, TOK / 128);
        gemm_tc_kernel<<<grid, 256>>>(gt, sa_in_w + (size_t)512 * DM, sa_in_b + 512,
                                      gbig + 512, TOK, 256, DM, 768, 0);
    }
    self_attn_kernel<<<BATCH * NQ, 128>>>(gbig, gx);
    {
        dim3 grid(256 / 128, TOK / 128);
        gemm_tc_kernel<<<grid, 256>>>(gx, sa_out_w, sa_out_b, gy, TOK, 256, DM, 256, 0);
    }
    add_ln_kernel<<<TOK, 256>>>(gt, gy, norm2_w, norm2_b, gt);

    // ---- stage 2: deformable cross-attention -------------------------------
    add_copy_kernel<<<(nTD + 255) / 256, 256>>>(gt, qpos, gq, (float*)0, nTD);
    {
        dim3 grid(256 / 128, VROWS / 128);
        gemm_tc_kernel<<<grid, 256>>>(src, ca_value_w, ca_value_b, gval, VROWS, 256, DM, 256, 0);
    }
    {
        long n = (long)VROWS * DM;
        mask_kernel<<<(unsigned)((n + 255) / 256), 256>>>(gval, mask, n);
    }
    {
        dim3 grid(256 / 128, TOK / 128);
        gemm_tc_kernel<<<grid, 256>>>(gq, ca_off_w, ca_off_b, gx, TOK, 256, DM, 256, 0);
    }
    {
        dim3 grid(128 / 128, TOK / 128);
        gemm_tc_kernel<<<grid, 256>>>(gq, ca_attw_w, ca_attw_b, gattw, TOK, 128, DM, 128, 0);
    }
    deform_kernel<<<TOK, 256>>>(gx, gattw, refp, gval, gq);
    {
        dim3 grid(256 / 128, TOK / 128);
        gemm_tc_kernel<<<grid, 256>>>(gq, ca_out_w, ca_out_b, gx, TOK, 256, DM, 256, 0);
    }
    add_ln_kernel<<<TOK, 256>>>(gt, gx, norm1_w, norm1_b, gt);

    // ---- stage 3: FFN ------------------------------------------------------
    {
        dim3 grid(DFFN / 128, TOK / 128);
        gemm_tc_kernel<<<grid, 256>>>(gt, lin1_w, lin1_b, gbig, TOK, DFFN, DM, DFFN, 1);
    }
    {
        dim3 grid(256 / 128, TOK / 128);
        gemm_tc_kernel<<<grid, 256>>>(gbig, lin2_w, lin2_b, gx, TOK, 256, DFFN, 256, 0);
    }
    add_ln_kernel<<<TOK, 256>>>(gt, gx, norm3_w, norm3_b, out);
}

// round 6
// speedup vs baseline: 2.7208x; 1.4147x over previous
#include <cuda_runtime.h>
#include <cuda_bf16.h>
#include <math.h>

#define DM 256
#define HEADS 8
#define DH 32
#define LEVELS 4
#define POINTS 4
#define DFFN 1024
#define BATCH 8
#define NQ 300
#define NC 16
#define LQ (NQ*NC)          // 4800
#define TOK (BATCH*LQ)      // 38400
#define LEN_IN 5440
#define VROWS (BATCH*LEN_IN) // 43520

// ---------------- scratch (static device memory; no runtime allocation) ----
__device__ float g_t[TOK*DM];
__device__ float g_q[TOK*DM];
__device__ float g_x[TOK*DM];
__device__ float g_y[TOK*DM];
__device__ float g_big[TOK*DFFN];
__device__ float g_val[VROWS*DM];
__device__ float g_attw[TOK*HEADS*LEVELS*POINTS];

// ---------------- bf16 helpers ---------------------------------------------
__device__ __forceinline__ unsigned pk(float x, float y) {
    __nv_bfloat162 v = __floats2bfloat162_rn(x, y);
    return *reinterpret_cast<unsigned*>(&v);
}

// split float4 (4 consecutive k) into hi/lo bf16 pair-words
__device__ __forceinline__ void cvt4(float4 v, unsigned& w0h, unsigned& w1h,
                                     unsigned& w0l, unsigned& w1l) {
    float x0 = v.x, x1 = v.y, x2 = v.z, x3 = v.w;
    float h0 = __bfloat162float(__float2bfloat16_rn(x0));
    float h1 = __bfloat162float(__float2bfloat16_rn(x1));
    float h2 = __bfloat162float(__float2bfloat16_rn(x2));
    float h3 = __bfloat162float(__float2bfloat16_rn(x3));
    w0h = pk(h0, h1); w1h = pk(h2, h3);
    w0l = pk(x0 - h0, x1 - h1); w1l = pk(x2 - h2, x3 - h3);
}

__device__ __forceinline__ void mma16(float* c, const unsigned* a, const unsigned* b) {
    asm volatile(
        "mma.sync.aligned.m16n8k16.row.col.f32.bf16.bf16.f32 "
        "{%0,%1,%2,%3}, {%4,%5,%6,%7}, {%8,%9}, {%0,%1,%2,%3};\n"
        : "+f"(c[0]), "+f"(c[1]), "+f"(c[2]), "+f"(c[3])
        : "r"(a[0]), "r"(a[1]), "r"(a[2]), "r"(a[3]), "r"(b[0]), "r"(b[1]));
}

// ---------------- 3xBF16 GEMM, 128x128 tile: C = A @ W^T + bias ------------
// Requires M%128==0, N%128==0, K%16==0. A:[M,K], W:[N,K], C:[M,ldc].
// fp32 emulated: ab = ah*bh + ah*bl + al*bh (dropped term ~2^-18 rel).
// smem words: [kp][m], kp = k/2 (pair packed in one 32-bit word).
#define SPAD 136
__global__ __launch_bounds__(256)
void gemm_bf3_kernel(const float* __restrict__ A,
                     const float* __restrict__ W,
                     const float* __restrict__ bias,
                     float* __restrict__ C,
                     int M, int N, int K, int ldc, int relu)
{
    __shared__ unsigned Ah[8][SPAD], Al[8][SPAD];
    __shared__ unsigned Bh[8][SPAD], Bl[8][SPAD];

    int tid  = threadIdx.x;                     // 256 threads = 8 warps
    int bm   = blockIdx.y << 7;
    int bn   = blockIdx.x << 7;
    int warp = tid >> 5, lane = tid & 31;
    int wm = warp & 1, wn = warp >> 1;          // 2 (M) x 4 (N) warps
    int g = lane >> 2, t = lane & 3;            // mma thread coords

    int lrow = tid >> 2;                        // 0..63
    int kc   = (tid & 3) << 2;                  // k offset: 0,4,8,12
    int kp   = (tid & 3) << 1;                  // k-pair index: 0,2,4,6

    const float* Ap0 = A + (size_t)(bm + lrow) * K + kc;
    const float* Ap1 = A + (size_t)(bm + lrow + 64) * K + kc;
    const float* Wp0 = W + (size_t)(bn + lrow) * K + kc;
    const float* Wp1 = W + (size_t)(bn + lrow + 64) * K + kc;

    float c[4][4][4];
#pragma unroll
    for (int mt = 0; mt < 4; mt++)
#pragma unroll
        for (int nt = 0; nt < 4; nt++)
#pragma unroll
            for (int r = 0; r < 4; r++) c[mt][nt][r] = 0.f;

    const int NIT = K >> 4;

    float4 pa0 = *(const float4*)(Ap0);
    float4 pa1 = *(const float4*)(Ap1);
    float4 pb0 = *(const float4*)(Wp0);
    float4 pb1 = *(const float4*)(Wp1);

    for (int it = 0; it < NIT; ++it) {
        // convert & store current tile
        {
            unsigned w0h, w1h, w0l, w1l;
            cvt4(pa0, w0h, w1h, w0l, w1l);
            Ah[kp][lrow]    = w0h; Ah[kp+1][lrow]    = w1h;
            Al[kp][lrow]    = w0l; Al[kp+1][lrow]    = w1l;
            cvt4(pa1, w0h, w1h, w0l, w1l);
            Ah[kp][lrow+64] = w0h; Ah[kp+1][lrow+64] = w1h;
            Al[kp][lrow+64] = w0l; Al[kp+1][lrow+64] = w1l;
            cvt4(pb0, w0h, w1h, w0l, w1l);
            Bh[kp][lrow]    = w0h; Bh[kp+1][lrow]    = w1h;
            Bl[kp][lrow]    = w0l; Bl[kp+1][lrow]    = w1l;
            cvt4(pb1, w0h, w1h, w0l, w1l);
            Bh[kp][lrow+64] = w0h; Bh[kp+1][lrow+64] = w1h;
            Bl[kp][lrow+64] = w0l; Bl[kp+1][lrow+64] = w1l;
        }
        __syncthreads();

        // prefetch next tile while computing
        if (it + 1 < NIT) {
            int off = (it + 1) << 4;
            pa0 = *(const float4*)(Ap0 + off);
            pa1 = *(const float4*)(Ap1 + off);
            pb0 = *(const float4*)(Wp0 + off);
            pb1 = *(const float4*)(Wp1 + off);
        }

        // one m16n8k16 covers the full 16-k tile
        {
            unsigned ah[4][4], al[4][4], bh[4][2], bl[4][2];
#pragma unroll
            for (int mt = 0; mt < 4; mt++) {
                int m = wm*64 + mt*16 + g;
                ah[mt][0] = Ah[t][m];   ah[mt][1] = Ah[t][m+8];
                ah[mt][2] = Ah[t+4][m]; ah[mt][3] = Ah[t+4][m+8];
                al[mt][0] = Al[t][m];   al[mt][1] = Al[t][m+8];
                al[mt][2] = Al[t+4][m]; al[mt][3] = Al[t+4][m+8];
            }
#pragma unroll
            for (int nt = 0; nt < 4; nt++) {
                int n = wn*32 + nt*8 + g;
                bh[nt][0] = Bh[t][n];   bh[nt][1] = Bh[t+4][n];
                bl[nt][0] = Bl[t][n];   bl[nt][1] = Bl[t+4][n];
            }
#pragma unroll
            for (int mt = 0; mt < 4; mt++)
#pragma unroll
                for (int nt = 0; nt < 4; nt++) {
                    mma16(c[mt][nt], ah[mt], bh[nt]);
                    mma16(c[mt][nt], ah[mt], bl[nt]);
                    mma16(c[mt][nt], al[mt], bh[nt]);
                }
        }
        __syncthreads();
    }

    // epilogue: bias (+relu)
    float lob = relu ? 0.f : __int_as_float(0xff800000);  // -inf if no relu
#pragma unroll
    for (int mt = 0; mt < 4; mt++) {
        int row0 = bm + wm*64 + mt*16 + g;
#pragma unroll
        for (int nt = 0; nt < 4; nt++) {
            int col = bn + wn*32 + nt*8 + 2*t;
            float2 bi = *(const float2*)(bias + col);
            float2 o0, o1;
            o0.x = fmaxf(c[mt][nt][0] + bi.x, lob);
            o0.y = fmaxf(c[mt][nt][1] + bi.y, lob);
            o1.x = fmaxf(c[mt][nt][2] + bi.x, lob);
            o1.y = fmaxf(c[mt][nt][3] + bi.y, lob);
            *(float2*)&C[(size_t)row0 * ldc + col]       = o0;
            *(float2*)&C[(size_t)(row0+8) * ldc + col]   = o1;
        }
    }
}

// ---------------- elementwise: q = a + b, optionally t = a ------------------
__global__ void add_copy_kernel(const float* __restrict__ a,
                                const float* __restrict__ b,
                                float* __restrict__ q,
                                float* __restrict__ t, int n)
{
    int i = blockIdx.x * blockDim.x + threadIdx.x;
    if (i < n) {
        float av = a[i];
        q[i] = av + b[i];
        if (t) t[i] = av;
    }
}

// ---------------- zero masked value rows -----------------------------------
__global__ void mask_kernel(float* __restrict__ val,
                            const unsigned char* __restrict__ mask, long n)
{
    long i = (long)blockIdx.x * blockDim.x + threadIdx.x;
    if (i < n) {
        if (mask[i >> 8]) val[i] = 0.f;
    }
}

// ---------------- self-attention over 16-token sequences --------------------
__global__ void self_attn_kernel(const float* __restrict__ qkv,
                                 float* __restrict__ out)
{
    __shared__ float sQ[NC][DM];
    __shared__ float sK[NC][DM];
    __shared__ float sV[NC][DM];
    int s = blockIdx.x;
    int tid = threadIdx.x;
    const float* base = qkv + (size_t)s * NC * 768;
    for (int idx = tid; idx < NC * DM; idx += 128) {
        int i = idx >> 8, cc = idx & 255;
        sQ[i][cc] = base[i * 768 + cc];
        sK[i][cc] = base[i * 768 + 256 + cc];
        sV[i][cc] = base[i * 768 + 512 + cc];
    }
    __syncthreads();

    int h = tid >> 4, i = tid & 15;
    const float scale = 0.1767766952966369f;  // 1/sqrt(32)
    float sc[NC];
    float mx = -1e30f;
#pragma unroll
    for (int j = 0; j < NC; j++) {
        float acc = 0.f;
#pragma unroll
        for (int d = 0; d < DH; d++) acc += sQ[i][h*DH + d] * sK[j][h*DH + d];
        acc *= scale;
        sc[j] = acc;
        mx = fmaxf(mx, acc);
    }
    float sum = 0.f;
#pragma unroll
    for (int j = 0; j < NC; j++) { sc[j] = expf(sc[j] - mx); sum += sc[j]; }
    float inv = 1.f / sum;
#pragma unroll
    for (int d = 0; d < DH; d++) {
        float acc = 0.f;
#pragma unroll
        for (int j = 0; j < NC; j++) acc += sc[j] * sV[j][h*DH + d];
        out[((size_t)s * NC + i) * DM + h*DH + d] = acc * inv;
    }
}

// ---------------- add + layernorm ------------------------------------------
__global__ void add_ln_kernel(const float* __restrict__ a,
                              const float* __restrict__ b,
                              const float* __restrict__ w,
                              const float* __restrict__ bb,
                              float* __restrict__ out)
{
    __shared__ float sred[8];
    __shared__ float smean, svar;
    int row = blockIdx.x, tid = threadIdx.x;    // 256 threads
    size_t idx = (size_t)row * DM + tid;
    float x = a[idx] + b[idx];
    float v = x;
#pragma unroll
    for (int o = 16; o; o >>= 1) v += __shfl_xor_sync(0xffffffffu, v, o);
    if ((tid & 31) == 0) sred[tid >> 5] = v;
    __syncthreads();
    if (tid == 0) {
        float s = 0.f;
#pragma unroll
        for (int k = 0; k < 8; k++) s += sred[k];
        smean = s * (1.f / DM);
    }
    __syncthreads();
    float d = x - smean;
    v = d * d;
#pragma unroll
    for (int o = 16; o; o >>= 1) v += __shfl_xor_sync(0xffffffffu, v, o);
    if ((tid & 31) == 0) sred[tid >> 5] = v;
    __syncthreads();
    if (tid == 0) {
        float s = 0.f;
#pragma unroll
        for (int k = 0; k < 8; k++) s += sred[k];
        svar = s * (1.f / DM);
    }
    __syncthreads();
    out[idx] = d * rsqrtf(svar + 1e-5f) * w[tid] + bb[tid];
}

// ---------------- deformable sampling ---------------------------------------
__global__ void deform_kernel(const float* __restrict__ off,
                              const float* __restrict__ attw,
                              const float* __restrict__ refp,
                              const float* __restrict__ val,
                              float* __restrict__ out)
{
    __shared__ float saw[HEADS][16];
    int token = blockIdx.x;
    int bidx  = token / LQ;
    int tid = threadIdx.x;
    int h = tid >> 5, lane = tid & 31;
    int j = lane & 15;

    float w = attw[(size_t)token * (HEADS*16) + h*16 + j];
    float mx = w;
#pragma unroll
    for (int o = 8; o; o >>= 1) mx = fmaxf(mx, __shfl_xor_sync(0xffffffffu, mx, o));
    float e = expf(w - mx);
    float s = e;
#pragma unroll
    for (int o = 8; o; o >>= 1) s += __shfl_xor_sync(0xffffffffu, s, o);
    if (lane < 16) saw[h][lane] = e / s;
    __syncwarp();

    const int Hs[4]     = {64, 32, 16, 8};
    const int Ws[4]     = {64, 32, 16, 8};
    const int starts[4] = {0, 4096, 5120, 5376};

    const float* offp = off + (size_t)token * DM + h * 32;
    const float* refb = refp + (size_t)token * (LEVELS*2);
    const float* vb = val + ((size_t)bidx * LEN_IN) * DM + h * DH + lane;

    float acc = 0.f;
#pragma unroll
    for (int l = 0; l < LEVELS; l++) {
        int H_ = Hs[l], W_ = Ws[l];
        float rx = refb[l*2 + 0], ry = refb[l*2 + 1];
        const float* vlev = vb + (size_t)starts[l] * DM;
#pragma unroll
        for (int p = 0; p < POINTS; p++) {
            float ox = offp[(l*4 + p)*2 + 0];
            float oy = offp[(l*4 + p)*2 + 1];
            float gx = (rx + ox / W_) * W_ - 0.5f;
            float gy = (ry + oy / H_) * H_ - 0.5f;
            float fx = floorf(gx), fy = floorf(gy);
            int x0 = (int)fx, y0 = (int)fy;
            float ax = gx - fx, ay = gy - fy;
            float aw = saw[h][l*4 + p];
            bool xin0 = (x0 >= 0) && (x0 < W_);
            bool xin1 = (x0 + 1 >= 0) && (x0 + 1 < W_);
            bool yin0 = (y0 >= 0) && (y0 < H_);
            bool yin1 = (y0 + 1 >= 0) && (y0 + 1 < H_);
            float v00 = (xin0 && yin0) ? vlev[(size_t)(y0*W_ + x0) * DM] : 0.f;
            float v01 = (xin1 && yin0) ? vlev[(size_t)(y0*W_ + x0 + 1) * DM] : 0.f;
            float v10 = (xin0 && yin1) ? vlev[(size_t)((y0+1)*W_ + x0) * DM] : 0.f;
            float v11 = (xin1 && yin1) ? vlev[(size_t)((y0+1)*W_ + x0 + 1) * DM] : 0.f;
            float sample = v00*(1.f-ax)*(1.f-ay) + v01*ax*(1.f-ay)
                         + v10*(1.f-ax)*ay       + v11*ax*ay;
            acc += aw * sample;
        }
    }
    out[(size_t)token * DM + h * DH + lane] = acc;
}

// ---------------------------------------------------------------------------
extern "C" void kernel_launch(void* const* d_in, const int* in_sizes, int n_in,
                              void* d_out, int out_size)
{
    const float* tgt   = (const float*)d_in[0];
    const float* qpos  = (const float*)d_in[1];
    const float* refp  = (const float*)d_in[2];
    const float* src   = (const float*)d_in[3];
    const unsigned char* mask = (const unsigned char*)d_in[6];
    const float* sa_in_w  = (const float*)d_in[7];
    const float* sa_in_b  = (const float*)d_in[8];
    const float* sa_out_w = (const float*)d_in[9];
    const float* sa_out_b = (const float*)d_in[10];
    const float* norm2_w  = (const float*)d_in[11];
    const float* norm2_b  = (const float*)d_in[12];
    const float* ca_value_w = (const float*)d_in[13];
    const float* ca_value_b = (const float*)d_in[14];
    const float* ca_off_w   = (const float*)d_in[15];
    const float* ca_off_b   = (const float*)d_in[16];
    const float* ca_attw_w  = (const float*)d_in[17];
    const float* ca_attw_b  = (const float*)d_in[18];
    const float* ca_out_w   = (const float*)d_in[19];
    const float* ca_out_b   = (const float*)d_in[20];
    const float* norm1_w    = (const float*)d_in[21];
    const float* norm1_b    = (const float*)d_in[22];
    const float* lin1_w     = (const float*)d_in[23];
    const float* lin1_b     = (const float*)d_in[24];
    const float* lin2_w     = (const float*)d_in[25];
    const float* lin2_b     = (const float*)d_in[26];
    const float* norm3_w    = (const float*)d_in[27];
    const float* norm3_b    = (const float*)d_in[28];
    float* out = (float*)d_out;

    float *gt, *gq, *gx, *gy, *gbig, *gval, *gattw;
    cudaGetSymbolAddress((void**)&gt,   g_t);
    cudaGetSymbolAddress((void**)&gq,   g_q);
    cudaGetSymbolAddress((void**)&gx,   g_x);
    cudaGetSymbolAddress((void**)&gy,   g_y);
    cudaGetSymbolAddress((void**)&gbig, g_big);
    cudaGetSymbolAddress((void**)&gval, g_val);
    cudaGetSymbolAddress((void**)&gattw, g_attw);

    const int nTD = TOK * DM;   // 9,830,400

    // ---- stage 1: self-attention -------------------------------------------
    add_copy_kernel<<<(nTD + 255) / 256, 256>>>(tgt, qpos, gq, gt, nTD);
    {
        dim3 grid(512 / 128, TOK / 128);
        gemm_bf3_kernel<<<grid, 256>>>(gq, sa_in_w, sa_in_b, gbig, TOK, 512, DM, 768, 0);
    }
    {
        dim3 grid(256 / 128, TOK / 128);
        gemm_bf3_kernel<<<grid, 256>>>(gt, sa_in_w + (size_t)512 * DM, sa_in_b + 512,
                                       gbig + 512, TOK, 256, DM, 768, 0);
    }
    self_attn_kernel<<<BATCH * NQ, 128>>>(gbig, gx);
    {
        dim3 grid(256 / 128, TOK / 128);
        gemm_bf3_kernel<<<grid, 256>>>(gx, sa_out_w, sa_out_b, gy, TOK, 256, DM, 256, 0);
    }
    add_ln_kernel<<<TOK, 256>>>(gt, gy, norm2_w, norm2_b, gt);

    // ---- stage 2: deformable cross-attention -------------------------------
    add_copy_kernel<<<(nTD + 255) / 256, 256>>>(gt, qpos, gq, (float*)0, nTD);
    {
        dim3 grid(256 / 128, VROWS / 128);
        gemm_bf3_kernel<<<grid, 256>>>(src, ca_value_w, ca_value_b, gval, VROWS, 256, DM, 256, 0);
    }
    {
        long n = (long)VROWS * DM;
        mask_kernel<<<(unsigned)((n + 255) / 256), 256>>>(gval, mask, n);
    }
    {
        dim3 grid(256 / 128, TOK / 128);
        gemm_bf3_kernel<<<grid, 256>>>(gq, ca_off_w, ca_off_b, gx, TOK, 256, DM, 256, 0);
    }
    {
        dim3 grid(128 / 128, TOK / 128);
        gemm_bf3_kernel<<<grid, 256>>>(gq, ca_attw_w, ca_attw_b, gattw, TOK, 128, DM, 128, 0);
    }
    deform_kernel<<<TOK, 256>>>(gx, gattw, refp, gval, gq);
    {
        dim3 grid(256 / 128, TOK / 128);
        gemm_bf3_kernel<<<grid, 256>>>(gq, ca_out_w, ca_out_b, gx, TOK, 256, DM, 256, 0);
    }
    add_ln_kernel<<<TOK, 256>>>(gt, gx, norm1_w, norm1_b, gt);

    // ---- stage 3: FFN ------------------------------------------------------
    {
        dim3 grid(DFFN / 128, TOK / 128);
        gemm_bf3_kernel<<<grid, 256>>>(gt, lin1_w, lin1_b, gbig, TOK, DFFN, DM, DFFN, 1);
    }
    {
        dim3 grid(256 / 128, TOK / 128);
        gemm_bf3_kernel<<<grid, 256>>>(gbig, lin2_w, lin2_b, gx, TOK, 256, DFFN, 256, 0);
    }
    add_ln_kernel<<<TOK, 256>>>(gt, gx, norm3_w, norm3_b, out);
}

// round 7
// speedup vs baseline: 2.8224x; 1.0373x over previous
#include <cuda_runtime.h>
#include <cuda_bf16.h>
#include <math.h>

#define DM 256
#define HEADS 8
#define DH 32
#define LEVELS 4
#define POINTS 4
#define DFFN 1024
#define BATCH 8
#define NQ 300
#define NC 16
#define LQ (NQ*NC)          // 4800
#define TOK (BATCH*LQ)      // 38400
#define LEN_IN 5440
#define VROWS (BATCH*LEN_IN) // 43520

// ---------------- scratch (static device memory; no runtime allocation) ----
__device__ float g_t[TOK*DM];
__device__ float g_q[TOK*DM];
__device__ float g_x[TOK*DM];
__device__ float g_y[TOK*DM];
__device__ float g_big[TOK*DFFN];
__device__ float g_val[VROWS*DM];
__device__ float g_attw[TOK*HEADS*LEVELS*POINTS];

// ---------------- bf16 helpers ---------------------------------------------
__device__ __forceinline__ unsigned pk(float x, float y) {
    __nv_bfloat162 v = __floats2bfloat162_rn(x, y);
    return *reinterpret_cast<unsigned*>(&v);
}

// split float4 (4 consecutive k) into hi/lo bf16 pair-words
__device__ __forceinline__ void cvt4(float4 v, unsigned& w0h, unsigned& w1h,
                                     unsigned& w0l, unsigned& w1l) {
    float x0 = v.x, x1 = v.y, x2 = v.z, x3 = v.w;
    float h0 = __bfloat162float(__float2bfloat16_rn(x0));
    float h1 = __bfloat162float(__float2bfloat16_rn(x1));
    float h2 = __bfloat162float(__float2bfloat16_rn(x2));
    float h3 = __bfloat162float(__float2bfloat16_rn(x3));
    w0h = pk(h0, h1); w1h = pk(h2, h3);
    w0l = pk(x0 - h0, x1 - h1); w1l = pk(x2 - h2, x3 - h3);
}

__device__ __forceinline__ void mma16(float* c, const unsigned* a, const unsigned* b) {
    asm volatile(
        "mma.sync.aligned.m16n8k16.row.col.f32.bf16.bf16.f32 "
        "{%0,%1,%2,%3}, {%4,%5,%6,%7}, {%8,%9}, {%0,%1,%2,%3};\n"
        : "+f"(c[0]), "+f"(c[1]), "+f"(c[2]), "+f"(c[3])
        : "r"(a[0]), "r"(a[1]), "r"(a[2]), "r"(a[3]), "r"(b[0]), "r"(b[1]));
}

__device__ __forceinline__ void ldsm4(unsigned& r0, unsigned& r1,
                                      unsigned& r2, unsigned& r3, unsigned addr) {
    asm volatile("ldmatrix.sync.aligned.m8n8.x4.shared.b16 {%0,%1,%2,%3}, [%4];"
                 : "=r"(r0), "=r"(r1), "=r"(r2), "=r"(r3) : "r"(addr));
}

// ---------------- 3xBF16 GEMM, 128x128 tile: C = A @ W^T + bias ------------
// Requires M%128==0, N%128==0, K%16==0. A:[M,K], W:[N,K], C:[M,ldc].
// fp32 emulated: ab = ah*bh + ah*bl + al*bh.
// smem: row-major [row][16 bf16], padded to 48B stride (conflict-free ldmatrix).
#define ROWW 12   // words per padded smem row (48 bytes)
__global__ __launch_bounds__(256)
void gemm_bf3_kernel(const float* __restrict__ A,
                     const float* __restrict__ W,
                     const float* __restrict__ bias,
                     float* __restrict__ C,
                     int M, int N, int K, int ldc, int relu)
{
    __shared__ unsigned Ah[128][ROWW], Al[128][ROWW];
    __shared__ unsigned Bh[128][ROWW], Bl[128][ROWW];

    int tid  = threadIdx.x;                     // 256 threads = 8 warps
    int bm   = blockIdx.y << 7;
    int bn   = blockIdx.x << 7;
    int warp = tid >> 5, lane = tid & 31;
    int wm = warp & 1, wn = warp >> 1;          // 2 (M) x 4 (N) warps
    int g = lane >> 2, t = lane & 3;

    int lrow = tid >> 2;                        // 0..63
    int kc   = (tid & 3) << 2;                  // 0,4,8,12

    const float* Ap0 = A + (size_t)(bm + lrow) * K + kc;
    const float* Ap1 = A + (size_t)(bm + lrow + 64) * K + kc;
    const float* Wp0 = W + (size_t)(bn + lrow) * K + kc;
    const float* Wp1 = W + (size_t)(bn + lrow + 64) * K + kc;

    unsigned saAh = (unsigned)__cvta_generic_to_shared(&Ah[0][0]);
    unsigned saAl = (unsigned)__cvta_generic_to_shared(&Al[0][0]);
    unsigned saBh = (unsigned)__cvta_generic_to_shared(&Bh[0][0]);
    unsigned saBl = (unsigned)__cvta_generic_to_shared(&Bl[0][0]);

    // ldmatrix addresses (loop-invariant)
    unsigned adA_h[4], adA_l[4], adB_h[2], adB_l[2];
    {
        int rA   = lane & 15;
        unsigned offA = (lane >> 4) << 4;       // 0 or 16 bytes (k halves)
#pragma unroll
        for (int mt = 0; mt < 4; mt++) {
            unsigned ro = (unsigned)(wm*64 + mt*16 + rA) * 48 + offA;
            adA_h[mt] = saAh + ro;
            adA_l[mt] = saAl + ro;
        }
#pragma unroll
        for (int p = 0; p < 2; p++) {
            int ntSel = 2*p + (lane >> 4);
            unsigned ro = (unsigned)(wn*32 + ntSel*8 + (lane & 7)) * 48
                        + (((lane >> 3) & 1) << 4);
            adB_h[p] = saBh + ro;
            adB_l[p] = saBl + ro;
        }
    }

    float c[4][4][4];
#pragma unroll
    for (int mt = 0; mt < 4; mt++)
#pragma unroll
        for (int nt = 0; nt < 4; nt++)
#pragma unroll
            for (int r = 0; r < 4; r++) c[mt][nt][r] = 0.f;

    const int NIT = K >> 4;

    float4 pa0 = *(const float4*)(Ap0);
    float4 pa1 = *(const float4*)(Ap1);
    float4 pb0 = *(const float4*)(Wp0);
    float4 pb1 = *(const float4*)(Wp1);

    int kw = kc >> 1;   // word offset within smem row

    for (int it = 0; it < NIT; ++it) {
        // convert & store current tile (row-major, padded)
        {
            unsigned w0h, w1h, w0l, w1l;
            cvt4(pa0, w0h, w1h, w0l, w1l);
            *(uint2*)&Ah[lrow][kw]    = make_uint2(w0h, w1h);
            *(uint2*)&Al[lrow][kw]    = make_uint2(w0l, w1l);
            cvt4(pa1, w0h, w1h, w0l, w1l);
            *(uint2*)&Ah[lrow+64][kw] = make_uint2(w0h, w1h);
            *(uint2*)&Al[lrow+64][kw] = make_uint2(w0l, w1l);
            cvt4(pb0, w0h, w1h, w0l, w1l);
            *(uint2*)&Bh[lrow][kw]    = make_uint2(w0h, w1h);
            *(uint2*)&Bl[lrow][kw]    = make_uint2(w0l, w1l);
            cvt4(pb1, w0h, w1h, w0l, w1l);
            *(uint2*)&Bh[lrow+64][kw] = make_uint2(w0h, w1h);
            *(uint2*)&Bl[lrow+64][kw] = make_uint2(w0l, w1l);
        }
        __syncthreads();

        // prefetch next tile while computing
        if (it + 1 < NIT) {
            int off = (it + 1) << 4;
            pa0 = *(const float4*)(Ap0 + off);
            pa1 = *(const float4*)(Ap1 + off);
            pb0 = *(const float4*)(Wp0 + off);
            pb1 = *(const float4*)(Wp1 + off);
        }

        // B fragments (hi + lo), 2 x ldmatrix.x4 each covering 2 n-tiles
        unsigned bh[4][2], bl[4][2];
        ldsm4(bh[0][0], bh[0][1], bh[1][0], bh[1][1], adB_h[0]);
        ldsm4(bh[2][0], bh[2][1], bh[3][0], bh[3][1], adB_h[1]);
        ldsm4(bl[0][0], bl[0][1], bl[1][0], bl[1][1], adB_l[0]);
        ldsm4(bl[2][0], bl[2][1], bl[3][0], bl[3][1], adB_l[1]);

#pragma unroll
        for (int mt = 0; mt < 4; mt++) {
            unsigned ah[4], al[4];
            ldsm4(ah[0], ah[1], ah[2], ah[3], adA_h[mt]);
            ldsm4(al[0], al[1], al[2], al[3], adA_l[mt]);
#pragma unroll
            for (int nt = 0; nt < 4; nt++) {
                mma16(c[mt][nt], ah, bh[nt]);
                mma16(c[mt][nt], ah, bl[nt]);
                mma16(c[mt][nt], al, bh[nt]);
            }
        }
        __syncthreads();
    }

    // epilogue: bias (+relu)
    float lob = relu ? 0.f : __int_as_float(0xff800000);  // -inf if no relu
#pragma unroll
    for (int mt = 0; mt < 4; mt++) {
        int row0 = bm + wm*64 + mt*16 + g;
#pragma unroll
        for (int nt = 0; nt < 4; nt++) {
            int col = bn + wn*32 + nt*8 + 2*t;
            float2 bi = *(const float2*)(bias + col);
            float2 o0, o1;
            o0.x = fmaxf(c[mt][nt][0] + bi.x, lob);
            o0.y = fmaxf(c[mt][nt][1] + bi.y, lob);
            o1.x = fmaxf(c[mt][nt][2] + bi.x, lob);
            o1.y = fmaxf(c[mt][nt][3] + bi.y, lob);
            *(float2*)&C[(size_t)row0 * ldc + col]       = o0;
            *(float2*)&C[(size_t)(row0+8) * ldc + col]   = o1;
        }
    }
}

// ---------------- elementwise: q = a + b, optionally t = a ------------------
__global__ void add_copy_kernel(const float* __restrict__ a,
                                const float* __restrict__ b,
                                float* __restrict__ q,
                                float* __restrict__ t, int n)
{
    int i = blockIdx.x * blockDim.x + threadIdx.x;
    if (i < n) {
        float av = a[i];
        q[i] = av + b[i];
        if (t) t[i] = av;
    }
}

// ---------------- zero masked value rows -----------------------------------
__global__ void mask_kernel(float* __restrict__ val,
                            const unsigned char* __restrict__ mask, long n)
{
    long i = (long)blockIdx.x * blockDim.x + threadIdx.x;
    if (i < n) {
        if (mask[i >> 8]) val[i] = 0.f;
    }
}

// ---------------- self-attention over 16-token sequences --------------------
__global__ void self_attn_kernel(const float* __restrict__ qkv,
                                 float* __restrict__ out)
{
    __shared__ float sQ[NC][DM];
    __shared__ float sK[NC][DM];
    __shared__ float sV[NC][DM];
    int s = blockIdx.x;
    int tid = threadIdx.x;
    const float* base = qkv + (size_t)s * NC * 768;
    for (int idx = tid; idx < NC * DM; idx += 128) {
        int i = idx >> 8, cc = idx & 255;
        sQ[i][cc] = base[i * 768 + cc];
        sK[i][cc] = base[i * 768 + 256 + cc];
        sV[i][cc] = base[i * 768 + 512 + cc];
    }
    __syncthreads();

    int h = tid >> 4, i = tid & 15;
    const float scale = 0.1767766952966369f;  // 1/sqrt(32)
    float sc[NC];
    float mx = -1e30f;
#pragma unroll
    for (int j = 0; j < NC; j++) {
        float acc = 0.f;
#pragma unroll
        for (int d = 0; d < DH; d++) acc += sQ[i][h*DH + d] * sK[j][h*DH + d];
        acc *= scale;
        sc[j] = acc;
        mx = fmaxf(mx, acc);
    }
    float sum = 0.f;
#pragma unroll
    for (int j = 0; j < NC; j++) { sc[j] = expf(sc[j] - mx); sum += sc[j]; }
    float inv = 1.f / sum;
#pragma unroll
    for (int d = 0; d < DH; d++) {
        float acc = 0.f;
#pragma unroll
        for (int j = 0; j < NC; j++) acc += sc[j] * sV[j][h*DH + d];
        out[((size_t)s * NC + i) * DM + h*DH + d] = acc * inv;
    }
}

// ---------------- add + layernorm ------------------------------------------
__global__ void add_ln_kernel(const float* __restrict__ a,
                              const float* __restrict__ b,
                              const float* __restrict__ w,
                              const float* __restrict__ bb,
                              float* __restrict__ out)
{
    __shared__ float sred[8];
    __shared__ float smean, svar;
    int row = blockIdx.x, tid = threadIdx.x;    // 256 threads
    size_t idx = (size_t)row * DM + tid;
    float x = a[idx] + b[idx];
    float v = x;
#pragma unroll
    for (int o = 16; o; o >>= 1) v += __shfl_xor_sync(0xffffffffu, v, o);
    if ((tid & 31) == 0) sred[tid >> 5] = v;
    __syncthreads();
    if (tid == 0) {
        float s = 0.f;
#pragma unroll
        for (int k = 0; k < 8; k++) s += sred[k];
        smean = s * (1.f / DM);
    }
    __syncthreads();
    float d = x - smean;
    v = d * d;
#pragma unroll
    for (int o = 16; o; o >>= 1) v += __shfl_xor_sync(0xffffffffu, v, o);
    if ((tid & 31) == 0) sred[tid >> 5] = v;
    __syncthreads();
    if (tid == 0) {
        float s = 0.f;
#pragma unroll
        for (int k = 0; k < 8; k++) s += sred[k];
        svar = s * (1.f / DM);
    }
    __syncthreads();
    out[idx] = d * rsqrtf(svar + 1e-5f) * w[tid] + bb[tid];
}

// ---------------- deformable sampling ---------------------------------------
__global__ void deform_kernel(const float* __restrict__ off,
                              const float* __restrict__ attw,
                              const float* __restrict__ refp,
                              const float* __restrict__ val,
                              float* __restrict__ out)
{
    __shared__ float saw[HEADS][16];
    int token = blockIdx.x;
    int bidx  = token / LQ;
    int tid = threadIdx.x;
    int h = tid >> 5, lane = tid & 31;
    int j = lane & 15;

    float w = attw[(size_t)token * (HEADS*16) + h*16 + j];
    float mx = w;
#pragma unroll
    for (int o = 8; o; o >>= 1) mx = fmaxf(mx, __shfl_xor_sync(0xffffffffu, mx, o));
    float e = expf(w - mx);
    float s = e;
#pragma unroll
    for (int o = 8; o; o >>= 1) s += __shfl_xor_sync(0xffffffffu, s, o);
    if (lane < 16) saw[h][lane] = e / s;
    __syncwarp();

    const int Hs[4]     = {64, 32, 16, 8};
    const int Ws[4]     = {64, 32, 16, 8};
    const int starts[4] = {0, 4096, 5120, 5376};

    const float* offp = off + (size_t)token * DM + h * 32;
    const float* refb = refp + (size_t)token * (LEVELS*2);
    const float* vb = val + ((size_t)bidx * LEN_IN) * DM + h * DH + lane;

    float acc = 0.f;
#pragma unroll
    for (int l = 0; l < LEVELS; l++) {
        int H_ = Hs[l], W_ = Ws[l];
        float rx = refb[l*2 + 0], ry = refb[l*2 + 1];
        const float* vlev = vb + (size_t)starts[l] * DM;
#pragma unroll
        for (int p = 0; p < POINTS; p++) {
            float ox = offp[(l*4 + p)*2 + 0];
            float oy = offp[(l*4 + p)*2 + 1];
            float gx = (rx + ox / W_) * W_ - 0.5f;
            float gy = (ry + oy / H_) * H_ - 0.5f;
            float fx = floorf(gx), fy = floorf(gy);
            int x0 = (int)fx, y0 = (int)fy;
            float ax = gx - fx, ay = gy - fy;
            float aw = saw[h][l*4 + p];
            bool xin0 = (x0 >= 0) && (x0 < W_);
            bool xin1 = (x0 + 1 >= 0) && (x0 + 1 < W_);
            bool yin0 = (y0 >= 0) && (y0 < H_);
            bool yin1 = (y0 + 1 >= 0) && (y0 + 1 < H_);
            float v00 = (xin0 && yin0) ? vlev[(size_t)(y0*W_ + x0) * DM] : 0.f;
            float v01 = (xin1 && yin0) ? vlev[(size_t)(y0*W_ + x0 + 1) * DM] : 0.f;
            float v10 = (xin0 && yin1) ? vlev[(size_t)((y0+1)*W_ + x0) * DM] : 0.f;
            float v11 = (xin1 && yin1) ? vlev[(size_t)((y0+1)*W_ + x0 + 1) * DM] : 0.f;
            float sample = v00*(1.f-ax)*(1.f-ay) + v01*ax*(1.f-ay)
                         + v10*(1.f-ax)*ay       + v11*ax*ay;
            acc += aw * sample;
        }
    }
    out[(size_t)token * DM + h * DH + lane] = acc;
}

// ---------------------------------------------------------------------------
extern "C" void kernel_launch(void* const* d_in, const int* in_sizes, int n_in,
                              void* d_out, int out_size)
{
    const float* tgt   = (const float*)d_in[0];
    const float* qpos  = (const float*)d_in[1];
    const float* refp  = (const float*)d_in[2];
    const float* src   = (const float*)d_in[3];
    const unsigned char* mask = (const unsigned char*)d_in[6];
    const float* sa_in_w  = (const float*)d_in[7];
    const float* sa_in_b  = (const float*)d_in[8];
    const float* sa_out_w = (const float*)d_in[9];
    const float* sa_out_b = (const float*)d_in[10];
    const float* norm2_w  = (const float*)d_in[11];
    const float* norm2_b  = (const float*)d_in[12];
    const float* ca_value_w = (const float*)d_in[13];
    const float* ca_value_b = (const float*)d_in[14];
    const float* ca_off_w   = (const float*)d_in[15];
    const float* ca_off_b   = (const float*)d_in[16];
    const float* ca_attw_w  = (const float*)d_in[17];
    const float* ca_attw_b  = (const float*)d_in[18];
    const float* ca_out_w   = (const float*)d_in[19];
    const float* ca_out_b   = (const float*)d_in[20];
    const float* norm1_w    = (const float*)d_in[21];
    const float* norm1_b    = (const float*)d_in[22];
    const float* lin1_w     = (const float*)d_in[23];
    const float* lin1_b     = (const float*)d_in[24];
    const float* lin2_w     = (const float*)d_in[25];
    const float* lin2_b     = (const float*)d_in[26];
    const float* norm3_w    = (const float*)d_in[27];
    const float* norm3_b    = (const float*)d_in[28];
    float* out = (float*)d_out;

    float *gt, *gq, *gx, *gy, *gbig, *gval, *gattw;
    cudaGetSymbolAddress((void**)&gt,   g_t);
    cudaGetSymbolAddress((void**)&gq,   g_q);
    cudaGetSymbolAddress((void**)&gx,   g_x);
    cudaGetSymbolAddress((void**)&gy,   g_y);
    cudaGetSymbolAddress((void**)&gbig, g_big);
    cudaGetSymbolAddress((void**)&gval, g_val);
    cudaGetSymbolAddress((void**)&gattw, g_attw);

    const int nTD = TOK * DM;   // 9,830,400

    // ---- stage 1: self-attention -------------------------------------------
    add_copy_kernel<<<(nTD + 255) / 256, 256>>>(tgt, qpos, gq, gt, nTD);
    {
        dim3 grid(512 / 128, TOK / 128);
        gemm_bf3_kernel<<<grid, 256>>>(gq, sa_in_w, sa_in_b, gbig, TOK, 512, DM, 768, 0);
    }
    {
        dim3 grid(256 / 128, TOK / 128);
        gemm_bf3_kernel<<<grid, 256>>>(gt, sa_in_w + (size_t)512 * DM, sa_in_b + 512,
                                       gbig + 512, TOK, 256, DM, 768, 0);
    }
    self_attn_kernel<<<BATCH * NQ, 128>>>(gbig, gx);
    {
        dim3 grid(256 / 128, TOK / 128);
        gemm_bf3_kernel<<<grid, 256>>>(gx, sa_out_w, sa_out_b, gy, TOK, 256, DM, 256, 0);
    }
    add_ln_kernel<<<TOK, 256>>>(gt, gy, norm2_w, norm2_b, gt);

    // ---- stage 2: deformable cross-attention -------------------------------
    add_copy_kernel<<<(nTD + 255) / 256, 256>>>(gt, qpos, gq, (float*)0, nTD);
    {
        dim3 grid(256 / 128, VROWS / 128);
        gemm_bf3_kernel<<<grid, 256>>>(src, ca_value_w, ca_value_b, gval, VROWS, 256, DM, 256, 0);
    }
    {
        long n = (long)VROWS * DM;
        mask_kernel<<<(unsigned)((n + 255) / 256), 256>>>(gval, mask, n);
    }
    {
        dim3 grid(256 / 128, TOK / 128);
        gemm_bf3_kernel<<<grid, 256>>>(gq, ca_off_w, ca_off_b, gx, TOK, 256, DM, 256, 0);
    }
    {
        dim3 grid(128 / 128, TOK / 128);
        gemm_bf3_kernel<<<grid, 256>>>(gq, ca_attw_w, ca_attw_b, gattw, TOK, 128, DM, 128, 0);
    }
    deform_kernel<<<TOK, 256>>>(gx, gattw, refp, gval, gq);
    {
        dim3 grid(256 / 128, TOK / 128);
        gemm_bf3_kernel<<<grid, 256>>>(gq, ca_out_w, ca_out_b, gx, TOK, 256, DM, 256, 0);
    }
    add_ln_kernel<<<TOK, 256>>>(gt, gx, norm1_w, norm1_b, gt);

    // ---- stage 3: FFN ------------------------------------------------------
    {
        dim3 grid(DFFN / 128, TOK / 128);
        gemm_bf3_kernel<<<grid, 256>>>(gt, lin1_w, lin1_b, gbig, TOK, DFFN, DM, DFFN, 1);
    }
    {
        dim3 grid(256 / 128, TOK / 128);
        gemm_bf3_kernel<<<grid, 256>>>(gbig, lin2_w, lin2_b, gx, TOK, 256, DFFN, 256, 0);
    }
    add_ln_kernel<<<TOK, 256>>>(gt, gx, norm3_w, norm3_b, out);
}